// round 2
// baseline (speedup 1.0000x reference)
#include <cuda_runtime.h>

// MFNet: two MFConv layers.
//   h1 = segment_sum(x[src], dst); deg = clip(indeg, 0, 10)
//   h  = relu(h1 @ W1[deg] + b1[deg] + x @ Wr1[deg])      [N,32]
//   h2 = segment_sum(h[src], dst)
//   out = h2 @ W2[deg] + b2[deg] + h @ Wr2[deg]           [N,64]
//
// Inputs (metadata order): x[N,128] f32, edge_index[2,E] int32 (JAX x64 is
// disabled, so the "int64" in the reference is demoted to int32),
//   W1[11,128,32], b1[11,32], Wr1[11,128,32], W2[11,32,64], b2[11,64], Wr2[11,32,64]

#define NMAX 100352
#define FIN  128
#define FH   32
#define FO   64
#define DMAX 10

// scratch (static __device__ — no allocations allowed)
__device__ __align__(16) float g_h1[NMAX * FIN];  // 51.4 MB
__device__ __align__(16) float g_h [NMAX * FH];   // 12.8 MB
__device__ __align__(16) float g_h2[NMAX * FH];   // 12.8 MB
__device__ int g_deg[NMAX];

__device__ __forceinline__ void red_add_v4(float* p, float4 v) {
    asm volatile("red.global.add.v4.f32 [%0], {%1, %2, %3, %4};"
                 :: "l"(p), "f"(v.x), "f"(v.y), "f"(v.z), "f"(v.w)
                 : "memory");
}

// ---------------------------------------------------------------- zero scratch
__global__ void k_zero(int N) {
    int i = blockIdx.x * blockDim.x + threadIdx.x;
    float4 z = make_float4(0.f, 0.f, 0.f, 0.f);
    int nh1 = N * (FIN / 4);   // float4 count of h1
    int nh2 = N * (FH / 4);
    if (i < nh1) reinterpret_cast<float4*>(g_h1)[i] = z;
    if (i < nh2) reinterpret_cast<float4*>(g_h2)[i] = z;
    if (i < N)   g_deg[i] = 0;
}

// ------------------------------------------------- layer-1 scatter (warp/edge)
// warp e: lanes cover the 128-float row of x[src[e]]; vector-red into h1[dst[e]].
__global__ void k_scatter1(const float* __restrict__ x,
                           const int* __restrict__ ei, int E, int N) {
    int t = blockIdx.x * blockDim.x + threadIdx.x;
    int e = t >> 5, lane = t & 31;
    if (e >= E) return;
    int s = __ldg(ei + e);
    int d = __ldg(ei + E + e);
    if ((unsigned)s >= (unsigned)N || (unsigned)d >= (unsigned)N) return;
    float4 v = *reinterpret_cast<const float4*>(x + (size_t)s * FIN + lane * 4);
    red_add_v4(g_h1 + (size_t)d * FIN + lane * 4, v);
    if (lane == 0) atomicAdd(g_deg + d, 1);
}

// ----------------------------------------------- layer-1 transform (warp/node)
// lane = output channel o (FH==32). Feature rows live in registers, broadcast
// via shfl; weight loads are coalesced 128B rows, hot in L1 (deg==10 for ~96%).
__global__ void k_trans1(const float* __restrict__ x,
                         const float* __restrict__ W1,
                         const float* __restrict__ b1,
                         const float* __restrict__ Wr1, int N) {
    int t = blockIdx.x * blockDim.x + threadIdx.x;
    int n = t >> 5, lane = t & 31;
    if (n >= N) return;
    int d = min(g_deg[n], DMAX);

    float hreg[4], xreg[4];
#pragma unroll
    for (int k = 0; k < 4; k++) {
        hreg[k] = g_h1[(size_t)n * FIN + k * 32 + lane];
        xreg[k] = __ldg(x + (size_t)n * FIN + k * 32 + lane);
    }
    const float* Wp  = W1  + d * FIN * FH;
    const float* Wrp = Wr1 + d * FIN * FH;
    float acc = __ldg(b1 + d * FH + lane);
#pragma unroll
    for (int k = 0; k < 4; k++) {
#pragma unroll
        for (int j = 0; j < 32; j++) {
            int f = k * 32 + j;
            acc = fmaf(__shfl_sync(0xffffffffu, hreg[k], j),
                       __ldg(Wp + f * FH + lane), acc);
            acc = fmaf(__shfl_sync(0xffffffffu, xreg[k], j),
                       __ldg(Wrp + f * FH + lane), acc);
        }
    }
    g_h[(size_t)n * FH + lane] = fmaxf(acc, 0.f);
}

// ------------------------------------------- layer-2 scatter (8 lanes / edge)
__global__ void k_scatter2(const int* __restrict__ ei, int E, int N) {
    int t = blockIdx.x * blockDim.x + threadIdx.x;
    int e = t >> 3;              // 8 lanes per edge: 8 x float4 = 32 floats
    int f4 = (t & 7) * 4;
    if (e >= E) return;
    int s = __ldg(ei + e);
    int d = __ldg(ei + E + e);
    if ((unsigned)s >= (unsigned)N || (unsigned)d >= (unsigned)N) return;
    float4 v = *reinterpret_cast<const float4*>(g_h + (size_t)s * FH + f4);
    red_add_v4(g_h2 + (size_t)d * FH + f4, v);
}

// ----------------------------------------------- layer-2 transform (warp/node)
// lane handles outputs o=lane and o=lane+32 (FO==64).
__global__ void k_trans2(const float* __restrict__ W2,
                         const float* __restrict__ b2,
                         const float* __restrict__ Wr2,
                         float* __restrict__ out, int N) {
    int t = blockIdx.x * blockDim.x + threadIdx.x;
    int n = t >> 5, lane = t & 31;
    if (n >= N) return;
    int d = min(g_deg[n], DMAX);

    float h2v = g_h2[(size_t)n * FH + lane];
    float hv  = g_h [(size_t)n * FH + lane];
    const float* Wp  = W2  + d * FH * FO;
    const float* Wrp = Wr2 + d * FH * FO;
    float acc0 = __ldg(b2 + d * FO + lane);
    float acc1 = __ldg(b2 + d * FO + 32 + lane);
#pragma unroll
    for (int j = 0; j < 32; j++) {
        float a = __shfl_sync(0xffffffffu, h2v, j);
        float c = __shfl_sync(0xffffffffu, hv,  j);
        acc0 = fmaf(a, __ldg(Wp  + j * FO + lane),      acc0);
        acc1 = fmaf(a, __ldg(Wp  + j * FO + 32 + lane), acc1);
        acc0 = fmaf(c, __ldg(Wrp + j * FO + lane),      acc0);
        acc1 = fmaf(c, __ldg(Wrp + j * FO + 32 + lane), acc1);
    }
    out[(size_t)n * FO + lane]      = acc0;
    out[(size_t)n * FO + 32 + lane] = acc1;
}

// ============================================================================
extern "C" void kernel_launch(void* const* d_in, const int* in_sizes, int n_in,
                              void* d_out, int out_size) {
    const float* x   = (const float*)d_in[0];
    const int*   ei  = (const int*)d_in[1];     // int32! (JAX x64 disabled)
    const float* W1  = (const float*)d_in[2];
    const float* b1  = (const float*)d_in[3];
    const float* Wr1 = (const float*)d_in[4];
    const float* W2  = (const float*)d_in[5];
    const float* b2  = (const float*)d_in[6];
    const float* Wr2 = (const float*)d_in[7];
    float* out = (float*)d_out;

    int N = in_sizes[0] / FIN;
    int E = in_sizes[1] / 2;
    if (N > NMAX) N = NMAX;  // safety clamp (problem is fixed at N=100000)

    const int TPB = 256;
    int zthreads = N * 32;  // covers N*FIN/4 float4s of h1 (largest)
    k_zero<<<(zthreads + TPB - 1) / TPB, TPB>>>(N);

    long long s1threads = (long long)E * 32;
    k_scatter1<<<(unsigned)((s1threads + TPB - 1) / TPB), TPB>>>(x, ei, E, N);

    int tthreads = N * 32;
    k_trans1<<<(tthreads + TPB - 1) / TPB, TPB>>>(x, W1, b1, Wr1, N);

    long long s2threads = (long long)E * 8;
    k_scatter2<<<(unsigned)((s2threads + TPB - 1) / TPB), TPB>>>(ei, E, N);

    k_trans2<<<(tthreads + TPB - 1) / TPB, TPB>>>(W2, b2, Wr2, out, N);
}

// round 3
// speedup vs baseline: 1.5081x; 1.5081x over previous
#include <cuda_runtime.h>

// MFNet: two MFConv layers, CSR-gather formulation (no atomics on features).
//   deg/CSR built by counting sort on dst.
//   h  = relu(gather_sum(x)[n] @ W1[deg] + b1[deg] + x[n] @ Wr1[deg])   [N,32]
//   out = gather_sum(h)[n] @ W2[deg] + b2[deg] + h[n] @ Wr2[deg]       [N,64]
//
// Inputs: x[N,128] f32, edge_index[2,E] int32, W1[11,128,32], b1[11,32],
//         Wr1[11,128,32], W2[11,32,64], b2[11,64], Wr2[11,32,64]

#define NMAX 100352
#define EMAX 1664000
#define FIN  128
#define FH   32
#define FO   64
#define DMAX 10
#define TPB  256

// scratch (static __device__ — no allocations allowed)
__device__ int g_deg[NMAX];
__device__ int g_partial[1024];
__device__ int g_rowptr[NMAX + 1];
__device__ int g_cursor[NMAX];
__device__ int g_csr[EMAX];
__device__ __align__(16) float g_h[NMAX * FH];   // 12.8 MB

// ---------------------------------------------------------------- degree hist
__global__ void k_zerodeg(int N) {
    int i = blockIdx.x * blockDim.x + threadIdx.x;
    if (i < N) g_deg[i] = 0;
}

__global__ void k_hist(const int* __restrict__ ei, int E, int N) {
    int e = blockIdx.x * blockDim.x + threadIdx.x;
    if (e >= E) return;
    int d = __ldg(ei + E + e);
    if ((unsigned)d < (unsigned)N) atomicAdd(g_deg + d, 1);
}

// -------------------------------------------------------- 3-phase excl. scan
__global__ void k_blocksum(int N) {
    __shared__ int sh[TPB];
    int n = blockIdx.x * TPB + threadIdx.x;
    sh[threadIdx.x] = (n < N) ? g_deg[n] : 0;
    __syncthreads();
    for (int s = TPB / 2; s > 0; s >>= 1) {
        if (threadIdx.x < s) sh[threadIdx.x] += sh[threadIdx.x + s];
        __syncthreads();
    }
    if (threadIdx.x == 0) g_partial[blockIdx.x] = sh[0];
}

__global__ void k_scanpartial(int nb) {
    __shared__ int sh[1024];
    int i = threadIdx.x;
    int v = (i < nb) ? g_partial[i] : 0;
    sh[i] = v;
    __syncthreads();
    for (int off = 1; off < 1024; off <<= 1) {
        int t = (i >= off) ? sh[i - off] : 0;
        __syncthreads();
        sh[i] += t;
        __syncthreads();
    }
    if (i < nb) g_partial[i] = sh[i] - v;   // exclusive block offsets
}

__global__ void k_writeptr(int N, int E) {
    __shared__ int sh[TPB];
    int n = blockIdx.x * TPB + threadIdx.x;
    int v = (n < N) ? g_deg[n] : 0;
    sh[threadIdx.x] = v;
    __syncthreads();
    for (int off = 1; off < TPB; off <<= 1) {
        int t = (threadIdx.x >= off) ? sh[threadIdx.x - off] : 0;
        __syncthreads();
        sh[threadIdx.x] += t;
        __syncthreads();
    }
    int excl = sh[threadIdx.x] - v + g_partial[blockIdx.x];
    if (n < N) { g_rowptr[n] = excl; g_cursor[n] = excl; }
    if (n == 0) g_rowptr[N] = E;
}

// --------------------------------------------------------- CSR edge placement
__global__ void k_place(const int* __restrict__ ei, int E, int N) {
    int e = blockIdx.x * blockDim.x + threadIdx.x;
    if (e >= E) return;
    int s = __ldg(ei + e);
    int d = __ldg(ei + E + e);
    if ((unsigned)s >= (unsigned)N || (unsigned)d >= (unsigned)N) return;
    int pos = atomicAdd(g_cursor + d, 1);
    g_csr[pos] = s;
}

// --------------------------------------- layer 1: fused gather + transform
// warp per node. Lane holds features [4*lane, 4*lane+4) of the neighbor sum
// (float4 accumulate over coalesced 512B rows), broadcasts via shfl into the
// 128x32 matvec; lane = output channel. Weights L1-hot (deg==10 bucket ~96%).
__global__ void k_fused1(const float* __restrict__ x,
                         const float* __restrict__ W1,
                         const float* __restrict__ b1,
                         const float* __restrict__ Wr1, int N) {
    int t = blockIdx.x * blockDim.x + threadIdx.x;
    int n = t >> 5, lane = t & 31;
    if (n >= N) return;
    int beg = g_rowptr[n], end = g_rowptr[n + 1];
    int d = min(end - beg, DMAX);

    float a0 = 0.f, a1 = 0.f, a2 = 0.f, a3 = 0.f;
    for (int j = beg; j < end; j++) {
        int s = __ldg(g_csr + j);
        float4 v = *reinterpret_cast<const float4*>(x + (size_t)s * FIN + lane * 4);
        a0 += v.x; a1 += v.y; a2 += v.z; a3 += v.w;
    }
    float4 xr = *reinterpret_cast<const float4*>(x + (size_t)n * FIN + lane * 4);

    const float* Wp  = W1  + d * FIN * FH;
    const float* Wrp = Wr1 + d * FIN * FH;
    float o = __ldg(b1 + d * FH + lane);
#pragma unroll
    for (int q = 0; q < 32; q++) {
        float h0 = __shfl_sync(0xffffffffu, a0, q);
        float h1 = __shfl_sync(0xffffffffu, a1, q);
        float h2 = __shfl_sync(0xffffffffu, a2, q);
        float h3 = __shfl_sync(0xffffffffu, a3, q);
        float x0 = __shfl_sync(0xffffffffu, xr.x, q);
        float x1 = __shfl_sync(0xffffffffu, xr.y, q);
        float x2 = __shfl_sync(0xffffffffu, xr.z, q);
        float x3 = __shfl_sync(0xffffffffu, xr.w, q);
        int f = q * 4;
        o = fmaf(h0, __ldg(Wp  + (f + 0) * FH + lane), o);
        o = fmaf(x0, __ldg(Wrp + (f + 0) * FH + lane), o);
        o = fmaf(h1, __ldg(Wp  + (f + 1) * FH + lane), o);
        o = fmaf(x1, __ldg(Wrp + (f + 1) * FH + lane), o);
        o = fmaf(h2, __ldg(Wp  + (f + 2) * FH + lane), o);
        o = fmaf(x2, __ldg(Wrp + (f + 2) * FH + lane), o);
        o = fmaf(h3, __ldg(Wp  + (f + 3) * FH + lane), o);
        o = fmaf(x3, __ldg(Wrp + (f + 3) * FH + lane), o);
    }
    g_h[(size_t)n * FH + lane] = fmaxf(o, 0.f);
}

// --------------------------------------- layer 2: fused gather + transform
// warp per node; lane holds one of 32 hidden channels, gathers 128B rows.
__global__ void k_fused2(const float* __restrict__ W2,
                         const float* __restrict__ b2,
                         const float* __restrict__ Wr2,
                         float* __restrict__ out, int N) {
    int t = blockIdx.x * blockDim.x + threadIdx.x;
    int n = t >> 5, lane = t & 31;
    if (n >= N) return;
    int beg = g_rowptr[n], end = g_rowptr[n + 1];
    int d = min(end - beg, DMAX);

    float hs = 0.f;
    for (int j = beg; j < end; j++) {
        int s = __ldg(g_csr + j);
        hs += g_h[(size_t)s * FH + lane];
    }
    float hn = g_h[(size_t)n * FH + lane];

    const float* Wp  = W2  + d * FH * FO;
    const float* Wrp = Wr2 + d * FH * FO;
    float acc0 = __ldg(b2 + d * FO + lane);
    float acc1 = __ldg(b2 + d * FO + 32 + lane);
#pragma unroll
    for (int j = 0; j < 32; j++) {
        float a = __shfl_sync(0xffffffffu, hs, j);
        float c = __shfl_sync(0xffffffffu, hn, j);
        acc0 = fmaf(a, __ldg(Wp  + j * FO + lane),      acc0);
        acc1 = fmaf(a, __ldg(Wp  + j * FO + 32 + lane), acc1);
        acc0 = fmaf(c, __ldg(Wrp + j * FO + lane),      acc0);
        acc1 = fmaf(c, __ldg(Wrp + j * FO + 32 + lane), acc1);
    }
    out[(size_t)n * FO + lane]      = acc0;
    out[(size_t)n * FO + 32 + lane] = acc1;
}

// ============================================================================
extern "C" void kernel_launch(void* const* d_in, const int* in_sizes, int n_in,
                              void* d_out, int out_size) {
    const float* x   = (const float*)d_in[0];
    const int*   ei  = (const int*)d_in[1];     // int32 (JAX x64 disabled)
    const float* W1  = (const float*)d_in[2];
    const float* b1  = (const float*)d_in[3];
    const float* Wr1 = (const float*)d_in[4];
    const float* W2  = (const float*)d_in[5];
    const float* b2  = (const float*)d_in[6];
    const float* Wr2 = (const float*)d_in[7];
    float* out = (float*)d_out;

    int N = in_sizes[0] / FIN;
    int E = in_sizes[1] / 2;
    if (N > NMAX) N = NMAX;
    if (E > EMAX) E = EMAX;

    int nb = (N + TPB - 1) / TPB;      // scan blocks (<= 392)
    int egrid = (E + TPB - 1) / TPB;
    int wgrid = (N * 32 + TPB - 1) / TPB;

    k_zerodeg<<<nb, TPB>>>(N);
    k_hist<<<egrid, TPB>>>(ei, E, N);
    k_blocksum<<<nb, TPB>>>(N);
    k_scanpartial<<<1, 1024>>>(nb);
    k_writeptr<<<nb, TPB>>>(N, E);
    k_place<<<egrid, TPB>>>(ei, E, N);
    k_fused1<<<wgrid, TPB>>>(x, W1, b1, Wr1, N);
    k_fused2<<<wgrid, TPB>>>(W2, b2, Wr2, out, N);
}

// round 5
// speedup vs baseline: 1.8440x; 1.2228x over previous
#include <cuda_runtime.h>

// MFNet: two MFConv layers, CSR-gather + packed-f32x2 matvec formulation.
//   h  = relu(gsum(x)[n] @ W1[deg] + b1[deg] + x[n] @ Wr1[deg])   [N,32]
//   out = gsum(h)[n] @ W2[deg] + b2[deg] + h[n] @ Wr2[deg]        [N,64]
// W/Wr pairs are pre-interleaved so one fma.rn.f32x2 drives both matvecs.
// Warp handles GRP=4 nodes so one weight load feeds 4 packed FMAs.

#define NMAX 100352
#define EMAX 1664000
#define FIN  128
#define FH   32
#define FO   64
#define DMAX 10
#define TPB  256
#define GRP  4

typedef unsigned long long u64;

// scratch (static __device__ — no allocations allowed)
__device__ int g_deg[NMAX];
__device__ int g_partial[1024];
__device__ int g_rowptr[NMAX + 1];
__device__ int g_cursor[NMAX];
__device__ int g_csr[EMAX];
__device__ __align__(16) float g_h[NMAX * FH];            // 12.8 MB
__device__ __align__(16) u64 g_Wp1[11 * FIN * FH];        // (W1,Wr1) interleaved
__device__ __align__(16) u64 g_Wp2[11 * FH * FO];         // (W2,Wr2) interleaved

__device__ __forceinline__ u64 pack2(float lo, float hi) {
    u64 r; asm("mov.b64 %0, {%1, %2};" : "=l"(r) : "f"(lo), "f"(hi)); return r;
}
__device__ __forceinline__ void unpack2(u64 v, float& lo, float& hi) {
    asm("mov.b64 {%0, %1}, %2;" : "=f"(lo), "=f"(hi) : "l"(v));
}
__device__ __forceinline__ void fma2(u64& d, u64 a, u64 b) {
    asm("fma.rn.f32x2 %0, %1, %2, %0;" : "+l"(d) : "l"(a), "l"(b));
}

// ------------------------------------------------------------- weight packing
__global__ void k_pack(const float* __restrict__ W1, const float* __restrict__ Wr1,
                       const float* __restrict__ W2, const float* __restrict__ Wr2) {
    int i = blockIdx.x * blockDim.x + threadIdx.x;
    if (i < 11 * FIN * FH) g_Wp1[i] = pack2(W1[i], Wr1[i]);
    if (i < 11 * FH * FO)  g_Wp2[i] = pack2(W2[i], Wr2[i]);
}

// ---------------------------------------------------------------- degree hist
__global__ void k_zerodeg(int N) {
    int i = blockIdx.x * blockDim.x + threadIdx.x;
    if (i < N) g_deg[i] = 0;
}
__global__ void k_hist(const int* __restrict__ ei, int E, int N) {
    int e = blockIdx.x * blockDim.x + threadIdx.x;
    if (e >= E) return;
    int d = __ldg(ei + E + e);
    if ((unsigned)d < (unsigned)N) atomicAdd(g_deg + d, 1);
}

// -------------------------------------------------------- 3-phase excl. scan
__global__ void k_blocksum(int N) {
    __shared__ int sh[TPB];
    int n = blockIdx.x * TPB + threadIdx.x;
    sh[threadIdx.x] = (n < N) ? g_deg[n] : 0;
    __syncthreads();
    for (int s = TPB / 2; s > 0; s >>= 1) {
        if (threadIdx.x < s) sh[threadIdx.x] += sh[threadIdx.x + s];
        __syncthreads();
    }
    if (threadIdx.x == 0) g_partial[blockIdx.x] = sh[0];
}
__global__ void k_scanpartial(int nb) {
    __shared__ int sh[1024];
    int i = threadIdx.x;
    int v = (i < nb) ? g_partial[i] : 0;
    sh[i] = v;
    __syncthreads();
    for (int off = 1; off < 1024; off <<= 1) {
        int t = (i >= off) ? sh[i - off] : 0;
        __syncthreads();
        sh[i] += t;
        __syncthreads();
    }
    if (i < nb) g_partial[i] = sh[i] - v;
}
__global__ void k_writeptr(int N, int E) {
    __shared__ int sh[TPB];
    int n = blockIdx.x * TPB + threadIdx.x;
    int v = (n < N) ? g_deg[n] : 0;
    sh[threadIdx.x] = v;
    __syncthreads();
    for (int off = 1; off < TPB; off <<= 1) {
        int t = (threadIdx.x >= off) ? sh[threadIdx.x - off] : 0;
        __syncthreads();
        sh[threadIdx.x] += t;
        __syncthreads();
    }
    int excl = sh[threadIdx.x] - v + g_partial[blockIdx.x];
    if (n < N) { g_rowptr[n] = excl; g_cursor[n] = excl; }
    if (n == 0) g_rowptr[N] = E;
}
__global__ void k_place(const int* __restrict__ ei, int E, int N) {
    int e = blockIdx.x * blockDim.x + threadIdx.x;
    if (e >= E) return;
    int s = __ldg(ei + e);
    int d = __ldg(ei + E + e);
    if ((unsigned)s >= (unsigned)N || (unsigned)d >= (unsigned)N) return;
    int pos = atomicAdd(g_cursor + d, 1);
    g_csr[pos] = s;
}

// --------------------------------------- layer 1: fused gather + transform
// Warp handles 4 nodes. Gather: lane owns features [4L,4L+4) of the neighbor
// sum (coalesced 512B rows). (hsum,x) pairs staged to smem; matvec: lane =
// output channel, one LDG.64 weight pair + 4 broadcast LDS + 4 FFMA2 per f.
__global__ __launch_bounds__(TPB) void k_fused1(const float* __restrict__ x,
                                                const float* __restrict__ b1, int N) {
    __shared__ u64 sh[TPB / 32][GRP * FIN];  // 8 warps x 4KB = 32KB
    int gw = (blockIdx.x * blockDim.x + threadIdx.x) >> 5;
    int lane = threadIdx.x & 31;
    u64* hx = sh[threadIdx.x >> 5];
    int base = gw * GRP;
    if (base >= N) return;

    int dg[GRP];
#pragma unroll
    for (int g = 0; g < GRP; g++) {
        int n = base + g;
        float a0 = 0.f, a1 = 0.f, a2 = 0.f, a3 = 0.f;
        float4 xr = make_float4(0.f, 0.f, 0.f, 0.f);
        int d = 0;
        if (n < N) {
            int beg = g_rowptr[n], end = g_rowptr[n + 1];
            d = min(end - beg, DMAX);
#pragma unroll 2
            for (int j = beg; j < end; j++) {
                int s = __ldg(g_csr + j);
                float4 v = *reinterpret_cast<const float4*>(x + (size_t)s * FIN + lane * 4);
                a0 += v.x; a1 += v.y; a2 += v.z; a3 += v.w;
            }
            xr = *reinterpret_cast<const float4*>(x + (size_t)n * FIN + lane * 4);
        }
        dg[g] = d;
        hx[g * FIN + 4 * lane + 0] = pack2(a0, xr.x);
        hx[g * FIN + 4 * lane + 1] = pack2(a1, xr.y);
        hx[g * FIN + 4 * lane + 2] = pack2(a2, xr.z);
        hx[g * FIN + 4 * lane + 3] = pack2(a3, xr.w);
    }
    __syncwarp();

    u64 acc[GRP];
#pragma unroll
    for (int g = 0; g < GRP; g++)
        acc[g] = pack2(__ldg(b1 + dg[g] * FH + lane), 0.f);

    if (dg[0] == dg[1] && dg[1] == dg[2] && dg[2] == dg[3]) {
        const u64* Wp = g_Wp1 + dg[0] * FIN * FH;
#pragma unroll 8
        for (int f = 0; f < FIN; f++) {
            u64 wv = __ldg(Wp + f * FH + lane);
            fma2(acc[0], hx[0 * FIN + f], wv);
            fma2(acc[1], hx[1 * FIN + f], wv);
            fma2(acc[2], hx[2 * FIN + f], wv);
            fma2(acc[3], hx[3 * FIN + f], wv);
        }
    } else {
#pragma unroll
        for (int g = 0; g < GRP; g++) {
            const u64* Wp = g_Wp1 + dg[g] * FIN * FH;
#pragma unroll 8
            for (int f = 0; f < FIN; f++)
                fma2(acc[g], hx[g * FIN + f], __ldg(Wp + f * FH + lane));
        }
    }
#pragma unroll
    for (int g = 0; g < GRP; g++) {
        int n = base + g;
        if (n < N) {
            float lo, hi; unpack2(acc[g], lo, hi);
            g_h[(size_t)n * FH + lane] = fmaxf(lo + hi, 0.f);
        }
    }
}

// --------------------------------------- layer 2: fused gather + transform
__global__ __launch_bounds__(TPB) void k_fused2(const float* __restrict__ b2,
                                                float* __restrict__ out, int N) {
    __shared__ u64 sh[TPB / 32][GRP * FH];   // 8 warps x 1KB
    int gw = (blockIdx.x * blockDim.x + threadIdx.x) >> 5;
    int lane = threadIdx.x & 31;
    u64* hh = sh[threadIdx.x >> 5];
    int base = gw * GRP;
    if (base >= N) return;

    int dg[GRP];
#pragma unroll
    for (int g = 0; g < GRP; g++) {
        int n = base + g;
        float hs = 0.f, hn = 0.f;
        int d = 0;
        if (n < N) {
            int beg = g_rowptr[n], end = g_rowptr[n + 1];
            d = min(end - beg, DMAX);
#pragma unroll 2
            for (int j = beg; j < end; j++) {
                int s = __ldg(g_csr + j);
                hs += g_h[(size_t)s * FH + lane];
            }
            hn = g_h[(size_t)n * FH + lane];
        }
        dg[g] = d;
        hh[g * FH + lane] = pack2(hs, hn);
    }
    __syncwarp();

    u64 acc0[GRP], acc1[GRP];
#pragma unroll
    for (int g = 0; g < GRP; g++) {
        acc0[g] = pack2(__ldg(b2 + dg[g] * FO + lane), 0.f);
        acc1[g] = pack2(__ldg(b2 + dg[g] * FO + 32 + lane), 0.f);
    }

    if (dg[0] == dg[1] && dg[1] == dg[2] && dg[2] == dg[3]) {
        const u64* Wp = g_Wp2 + dg[0] * FH * FO;
#pragma unroll 8
        for (int j = 0; j < FH; j++) {
            u64 w0 = __ldg(Wp + j * FO + lane);
            u64 w1 = __ldg(Wp + j * FO + 32 + lane);
#pragma unroll
            for (int g = 0; g < GRP; g++) {
                u64 hv = hh[g * FH + j];
                fma2(acc0[g], hv, w0);
                fma2(acc1[g], hv, w1);
            }
        }
    } else {
#pragma unroll
        for (int g = 0; g < GRP; g++) {
            const u64* Wp = g_Wp2 + dg[g] * FH * FO;
#pragma unroll 8
            for (int j = 0; j < FH; j++) {
                u64 hv = hh[g * FH + j];
                fma2(acc0[g], hv, __ldg(Wp + j * FO + lane));
                fma2(acc1[g], hv, __ldg(Wp + j * FO + 32 + lane));
            }
        }
    }
#pragma unroll
    for (int g = 0; g < GRP; g++) {
        int n = base + g;
        if (n < N) {
            float lo, hi;
            unpack2(acc0[g], lo, hi);
            out[(size_t)n * FO + lane] = lo + hi;
            unpack2(acc1[g], lo, hi);
            out[(size_t)n * FO + 32 + lane] = lo + hi;
        }
    }
}

// ============================================================================
extern "C" void kernel_launch(void* const* d_in, const int* in_sizes, int n_in,
                              void* d_out, int out_size) {
    const float* x   = (const float*)d_in[0];
    const int*   ei  = (const int*)d_in[1];     // int32 (JAX x64 disabled)
    const float* W1  = (const float*)d_in[2];
    const float* b1  = (const float*)d_in[3];
    const float* Wr1 = (const float*)d_in[4];
    const float* W2  = (const float*)d_in[5];
    const float* b2  = (const float*)d_in[6];
    const float* Wr2 = (const float*)d_in[7];
    float* out = (float*)d_out;

    int N = in_sizes[0] / FIN;
    int E = in_sizes[1] / 2;
    if (N > NMAX) N = NMAX;
    if (E > EMAX) E = EMAX;

    int nb = (N + TPB - 1) / TPB;
    int egrid = (E + TPB - 1) / TPB;
    int nwarps = (N + GRP - 1) / GRP;
    int fgrid = (nwarps * 32 + TPB - 1) / TPB;

    k_pack<<<(11 * FIN * FH + TPB - 1) / TPB, TPB>>>(W1, Wr1, W2, Wr2);
    k_zerodeg<<<nb, TPB>>>(N);
    k_hist<<<egrid, TPB>>>(ei, E, N);
    k_blocksum<<<nb, TPB>>>(N);
    k_scanpartial<<<1, 1024>>>(nb);
    k_writeptr<<<nb, TPB>>>(N, E);
    k_place<<<egrid, TPB>>>(ei, E, N);
    k_fused1<<<fgrid, TPB>>>(x, b1, N);
    k_fused2<<<fgrid, TPB>>>(b2, out, N);
}